// round 12
// baseline (speedup 1.0000x reference)
#include <cuda_runtime.h>
#include <cstdint>

#define Bv   32
#define Tv   168
#define NHv  32
#define NMv  64
#define Ev   384
#define HGv  64
#define HLv  128
#define G4   512
#define FUT  24
#define GT   (Bv*Tv)

#define RES   104        // Whh rows resident in smem (kC)
#define NREG  24         // Whh rows resident in registers (kC)

typedef unsigned long long u64t;

// -------- scratch --------
__device__ float d_whhT[(size_t)NHv * HLv * G4];          // [s][k][j]
__device__ u64t  d_wih2u[(size_t)NHv * HGv * G4];         // [s][k][j] (w,w) pairs
__device__ float d_xproj[(size_t)NHv * 4 * Tv * G4 * 8];  // [(s*4+bg)][t][j][bi]
__device__ float d_hfin[NHv * Bv * HLv];                  // [s][b][n]
__device__ int   d_csr_off[NHv + 1];                      // edges grouped by hydro dst
__device__ int   d_csr_src[Ev];

__device__ __forceinline__ u64t pk2(float x, float y) {
    u64t r; asm("mov.b64 %0,{%1,%2};" : "=l"(r) : "f"(x), "f"(y)); return r;
}
__device__ __forceinline__ float2 up2(u64t v) {
    float2 f; asm("mov.b64 {%0,%1},%2;" : "=f"(f.x), "=f"(f.y) : "l"(v)); return f;
}
__device__ __forceinline__ u64t fma2(u64t a, u64t b, u64t c) {
    u64t r; asm("fma.rn.f32x2 %0,%1,%2,%3;" : "=l"(r) : "l"(a), "l"(b), "l"(c)); return r;
}
__device__ __forceinline__ float sigf(float x) {
    return __fdividef(1.0f, 1.0f + __expf(-x));
}
__device__ __forceinline__ float tanhfast(float x) {
    return 1.0f - 2.0f * __fdividef(1.0f, __expf(2.0f * x) + 1.0f);
}
__device__ __forceinline__ float lrelu(float v) { return v > 0.0f ? v : 0.01f * v; }

// =====================================================================
// kE: dtype-robust edge decode + PARALLEL smem CSR build.
// Counting/placement per hydro dst done by 32 threads over smem copies
// (broadcast reads). Same per-dst edge order as before => same numerics.
// =====================================================================
__global__ void kE(const void* __restrict__ ei) {
    __shared__ int nz;
    __shared__ short es[Ev], ed[Ev];
    __shared__ int offs[NHv + 1], cnts[NHv];
    const int* w = (const int*)ei;
    int tid = threadIdx.x;  // 256
    if (tid == 0) nz = 0;
    __syncthreads();
    int cnt = 0;
    for (int i = tid; i < 2 * Ev; i += 256)
        if ((i & 1) && w[i] == 0) cnt++;
    for (int o = 16; o > 0; o >>= 1) cnt += __shfl_down_sync(0xffffffffu, cnt, o);
    if ((tid & 31) == 0) atomicAdd(&nz, cnt);
    __syncthreads();
    bool is64 = (nz > 100);
    for (int e = tid; e < Ev; e += 256) {
        es[e] = (short)(is64 ? (int)((const long long*)ei)[e] : w[e]);
        ed[e] = (short)(is64 ? (int)((const long long*)ei)[Ev + e] : w[Ev + e]);
    }
    __syncthreads();
    if (tid < NHv) {
        int c = 0;
        for (int e = 0; e < Ev; e++)
            if (ed[e] == tid) c++;
        cnts[tid] = c;
    }
    __syncthreads();
    if (tid == 0) {
        int a = 0;
        for (int s2 = 0; s2 < NHv; s2++) { offs[s2] = a; a += cnts[s2]; }
        offs[NHv] = a;
        d_csr_off[NHv] = a;
    }
    __syncthreads();
    if (tid < NHv) {
        d_csr_off[tid] = offs[tid];
        int p = offs[tid];
        for (int e = 0; e < Ev; e++)
            if (ed[e] == tid) d_csr_src[p++] = (int)es[e];
    }
}

// =====================================================================
// kT: tiled per-station transpose [s][J][K] -> [s][K][J].
// which=0: whh -> d_whhT (float). which=1: wih -> d_wih2u (dup (w,w) u64).
// =====================================================================
__global__ void kT(const float* __restrict__ src, int J, int K, int which) {
    __shared__ float tile[32][33];
    int s = blockIdx.z;
    int k0 = blockIdx.x * 32, j0 = blockIdx.y * 32;
    int tx = threadIdx.x, ty = threadIdx.y;
    const float* S = src + (size_t)s * J * K;
    #pragma unroll
    for (int dy = 0; dy < 32; dy += 8)
        tile[ty + dy][tx] = S[(size_t)(j0 + ty + dy) * K + (k0 + tx)];
    __syncthreads();
    if (which == 0) {
        float* D = d_whhT + (size_t)s * J * K;
        #pragma unroll
        for (int dy = 0; dy < 32; dy += 8)
            D[(size_t)(k0 + ty + dy) * J + (j0 + tx)] = tile[tx][ty + dy];
    } else {
        u64t* D = d_wih2u + (size_t)s * J * K;
        #pragma unroll
        for (int dy = 0; dy < 32; dy += 8) {
            float v = tile[tx][ty + dy];
            D[(size_t)(k0 + ty + dy) * J + (j0 + tx)] = pk2(v, v);
        }
    }
}

// =====================================================================
// kB: fused GNN + input projection. grid (t, s, z=bhalf), 128 threads.
// Weights read as pre-duplicated (w,w) u64 pairs -> zero packing MOVs.
// =====================================================================
__global__ void __launch_bounds__(128) kB(
        const float* __restrict__ hyd, const float* __restrict__ met,
        const float* __restrict__ Wr, const float* __restrict__ Wl,
        const float* __restrict__ bg,
        const float* __restrict__ bih, const float* __restrict__ bhh) {
    int t = blockIdx.x, s = blockIdx.y, z = blockIdx.z;
    int jj = threadIdx.x;
    int j0 = jj * 4;
    __shared__ float hloc[64 * 20];  // [k][b16], pad to 20
    __shared__ float xs[16], ag[16];
    __shared__ float wr[HGv], wl[HGv], bb[HGv];

    if (jj < HGv) { wr[jj] = Wr[jj]; wl[jj] = Wl[jj]; bb[jj] = bg[jj]; }
    if (jj >= 112) {  // one thread per batch: GNN scalar gather via CSR
        int b = jj - 112;
        int gb = z * 16 + b;
        const float* hrow = hyd + ((size_t)gb * Tv + t) * NHv;
        const float* mrow = met + ((size_t)gb * Tv + t) * NMv;
        xs[b] = hrow[s];
        float a = 0.0f;
        int e0 = d_csr_off[s], e1 = d_csr_off[s + 1];
        for (int e = e0; e < e1; e++) {
            int sr = d_csr_src[e];
            a += (sr < NHv) ? hrow[sr] : mrow[sr - NHv];
        }
        ag[b] = a;
    }
    __syncthreads();

    #pragma unroll
    for (int r = 0; r < 8; r++) {
        int idx = jj + r * 128;          // 1024 = 64k x 16b
        int k = idx >> 4, b = idx & 15;
        hloc[k * 20 + b] = lrelu(xs[b] * wr[k] + ag[b] * wl[k] + bb[k]);
    }
    __syncthreads();

    u64t acc[4][8];
    {
        float4 b1 = *reinterpret_cast<const float4*>(&bih[s * G4 + j0]);
        float4 b2 = *reinterpret_cast<const float4*>(&bhh[s * G4 + j0]);
        float bv[4] = {b1.x + b2.x, b1.y + b2.y, b1.z + b2.z, b1.w + b2.w};
        #pragma unroll
        for (int jl = 0; jl < 4; jl++) {
            u64t bb2 = pk2(bv[jl], bv[jl]);
            #pragma unroll
            for (int q = 0; q < 8; q++) acc[jl][q] = bb2;
        }
    }

    const u64t* wT2 = d_wih2u + (size_t)s * (HGv * G4);
    #pragma unroll 2
    for (int k = 0; k < 64; k++) {
        const ulonglong2* wp2 =
            reinterpret_cast<const ulonglong2*>(&wT2[(size_t)k * G4 + j0]);
        ulonglong2 wA = wp2[0], wB = wp2[1];   // dup(w_j0),dup(w_j1),dup(w_j2),dup(w_j3)
        const ulonglong2* hp = reinterpret_cast<const ulonglong2*>(&hloc[k * 20]);
        ulonglong2 h0 = hp[0], h1 = hp[1], h2 = hp[2], h3 = hp[3];
        acc[0][0] = fma2(h0.x, wA.x, acc[0][0]);
        acc[0][1] = fma2(h0.y, wA.x, acc[0][1]);
        acc[0][2] = fma2(h1.x, wA.x, acc[0][2]);
        acc[0][3] = fma2(h1.y, wA.x, acc[0][3]);
        acc[0][4] = fma2(h2.x, wA.x, acc[0][4]);
        acc[0][5] = fma2(h2.y, wA.x, acc[0][5]);
        acc[0][6] = fma2(h3.x, wA.x, acc[0][6]);
        acc[0][7] = fma2(h3.y, wA.x, acc[0][7]);
        acc[1][0] = fma2(h0.x, wA.y, acc[1][0]);
        acc[1][1] = fma2(h0.y, wA.y, acc[1][1]);
        acc[1][2] = fma2(h1.x, wA.y, acc[1][2]);
        acc[1][3] = fma2(h1.y, wA.y, acc[1][3]);
        acc[1][4] = fma2(h2.x, wA.y, acc[1][4]);
        acc[1][5] = fma2(h2.y, wA.y, acc[1][5]);
        acc[1][6] = fma2(h3.x, wA.y, acc[1][6]);
        acc[1][7] = fma2(h3.y, wA.y, acc[1][7]);
        acc[2][0] = fma2(h0.x, wB.x, acc[2][0]);
        acc[2][1] = fma2(h0.y, wB.x, acc[2][1]);
        acc[2][2] = fma2(h1.x, wB.x, acc[2][2]);
        acc[2][3] = fma2(h1.y, wB.x, acc[2][3]);
        acc[2][4] = fma2(h2.x, wB.x, acc[2][4]);
        acc[2][5] = fma2(h2.y, wB.x, acc[2][5]);
        acc[2][6] = fma2(h3.x, wB.x, acc[2][6]);
        acc[2][7] = fma2(h3.y, wB.x, acc[2][7]);
        acc[3][0] = fma2(h0.x, wB.y, acc[3][0]);
        acc[3][1] = fma2(h0.y, wB.y, acc[3][1]);
        acc[3][2] = fma2(h1.x, wB.y, acc[3][2]);
        acc[3][3] = fma2(h1.y, wB.y, acc[3][3]);
        acc[3][4] = fma2(h2.x, wB.y, acc[3][4]);
        acc[3][5] = fma2(h2.y, wB.y, acc[3][5]);
        acc[3][6] = fma2(h3.x, wB.y, acc[3][6]);
        acc[3][7] = fma2(h3.y, wB.y, acc[3][7]);
    }

    #pragma unroll
    for (int jl = 0; jl < 4; jl++) {
        #pragma unroll
        for (int half = 0; half < 2; half++) {
            float* base = &d_xproj[(((size_t)(s * 4 + z * 2 + half) * Tv + t) * G4
                                    + (j0 + jl)) * 8];
            ulonglong2 v0, v1;
            v0.x = acc[jl][half * 4 + 0]; v0.y = acc[jl][half * 4 + 1];
            v1.x = acc[jl][half * 4 + 2]; v1.y = acc[jl][half * 4 + 3];
            reinterpret_cast<ulonglong2*>(base)[0] = v0;
            reinterpret_cast<ulonglong2*>(base)[1] = v1;
        }
    }
}

// =====================================================================
// kC: recurrence (exact Round-8 winner). 128 blocks = (s, bg), 256 threads.
// =====================================================================
#define SMEM_C (RES * G4 * 4 + 2 * 1024 * 4)

extern __shared__ float smc[];

__global__ void __launch_bounds__(256) kC() {
    int blk = blockIdx.x;
    int s = blk >> 2, bg = blk & 3;
    int tid = threadIdx.x;
    int n = tid & 127;       // hidden unit
    int bh = tid >> 7;       // batch half: batches bh*4 .. bh*4+3

    float* wpk = smc;                   // [RES][128n][4g] packed
    float* hb0 = smc + RES * G4;        // [128n][8bi] double buffer
    float* hb1 = hb0 + 1024;

    const float* whhTs = d_whhT + (size_t)s * (HLv * G4);
    for (int i = tid; i < RES * G4; i += 256) {
        int k = i >> 9, q = i & 511;
        int nn = q >> 2, g = q & 3;
        wpk[i] = whhTs[(size_t)k * G4 + g * 128 + nn];
    }
    for (int i = tid; i < 1024; i += 256) hb0[i] = 0.0f;

    float wreg[NREG][4];
    #pragma unroll
    for (int r = 0; r < NREG; r++)
        #pragma unroll
        for (int g = 0; g < 4; g++)
            wreg[r][g] = whhTs[(size_t)(RES + r) * G4 + g * 128 + n];

    float c[4];
    #pragma unroll
    for (int q = 0; q < 4; q++) c[q] = 0.0f;

    const float* xp = d_xproj + (size_t)(s * 4 + bg) * Tv * (G4 * 8);
    float4 xc[4];
    #pragma unroll
    for (int g = 0; g < 4; g++)
        xc[g] = *reinterpret_cast<const float4*>(xp + (size_t)(n + g * 128) * 8 + bh * 4);

    float* hcur = hb0;
    float* hnxt = hb1;
    __syncthreads();

    for (int t = 0; t < Tv; t++) {
        u64t acc[8];
        #pragma unroll
        for (int g = 0; g < 4; g++) {
            acc[2 * g + 0] = pk2(xc[g].x, xc[g].y);
            acc[2 * g + 1] = pk2(xc[g].z, xc[g].w);
        }
        if (t < Tv - 1) {
            const float* xn = xp + (size_t)(t + 1) * (G4 * 8);
            #pragma unroll
            for (int g = 0; g < 4; g++)
                xc[g] = *reinterpret_cast<const float4*>(
                    xn + (size_t)(n + g * 128) * 8 + bh * 4);
        }

        #pragma unroll 4
        for (int k = 0; k < RES; k++) {
            float4 w = *reinterpret_cast<const float4*>(&wpk[k * G4 + n * 4]);
            ulonglong2 h = *reinterpret_cast<const ulonglong2*>(&hcur[k * 8 + bh * 4]);
            u64t W;
            W = pk2(w.x, w.x);
            acc[0] = fma2(h.x, W, acc[0]); acc[1] = fma2(h.y, W, acc[1]);
            W = pk2(w.y, w.y);
            acc[2] = fma2(h.x, W, acc[2]); acc[3] = fma2(h.y, W, acc[3]);
            W = pk2(w.z, w.z);
            acc[4] = fma2(h.x, W, acc[4]); acc[5] = fma2(h.y, W, acc[5]);
            W = pk2(w.w, w.w);
            acc[6] = fma2(h.x, W, acc[6]); acc[7] = fma2(h.y, W, acc[7]);
        }
        #pragma unroll
        for (int r = 0; r < NREG; r++) {
            int k = RES + r;
            ulonglong2 h = *reinterpret_cast<const ulonglong2*>(&hcur[k * 8 + bh * 4]);
            u64t W;
            W = pk2(wreg[r][0], wreg[r][0]);
            acc[0] = fma2(h.x, W, acc[0]); acc[1] = fma2(h.y, W, acc[1]);
            W = pk2(wreg[r][1], wreg[r][1]);
            acc[2] = fma2(h.x, W, acc[2]); acc[3] = fma2(h.y, W, acc[3]);
            W = pk2(wreg[r][2], wreg[r][2]);
            acc[4] = fma2(h.x, W, acc[4]); acc[5] = fma2(h.y, W, acc[5]);
            W = pk2(wreg[r][3], wreg[r][3]);
            acc[6] = fma2(h.x, W, acc[6]); acc[7] = fma2(h.y, W, acc[7]);
        }

        {
            float2 i0 = up2(acc[0]), i1 = up2(acc[1]);
            float2 f0 = up2(acc[2]), f1 = up2(acc[3]);
            float2 g0 = up2(acc[4]), g1 = up2(acc[5]);
            float2 o0 = up2(acc[6]), o1 = up2(acc[7]);
            float4 hv;
            c[0] = sigf(f0.x) * c[0] + sigf(i0.x) * tanhfast(g0.x);
            hv.x = sigf(o0.x) * tanhfast(c[0]);
            c[1] = sigf(f0.y) * c[1] + sigf(i0.y) * tanhfast(g0.y);
            hv.y = sigf(o0.y) * tanhfast(c[1]);
            c[2] = sigf(f1.x) * c[2] + sigf(i1.x) * tanhfast(g1.x);
            hv.z = sigf(o1.x) * tanhfast(c[2]);
            c[3] = sigf(f1.y) * c[3] + sigf(i1.y) * tanhfast(g1.y);
            hv.w = sigf(o1.y) * tanhfast(c[3]);
            *reinterpret_cast<float4*>(&hnxt[n * 8 + bh * 4]) = hv;
        }
        __syncthreads();
        float* tmp = hcur; hcur = hnxt; hnxt = tmp;
    }

    #pragma unroll
    for (int q = 0; q < 4; q++) {
        int b = bg * 8 + bh * 4 + q;
        d_hfin[((size_t)s * Bv + b) * HLv + n] = hcur[n * 8 + bh * 4 + q];
    }
}

// =====================================================================
// kD: final linear + lrelu
// =====================================================================
__global__ void kD(const float* __restrict__ wlin, const float* __restrict__ blin,
                   float* __restrict__ out) {
    int s = blockIdx.x >> 5, b = blockIdx.x & 31;
    int f = threadIdx.x;
    __shared__ float hs[HLv];
    for (int i = threadIdx.x; i < HLv; i += 32)
        hs[i] = d_hfin[((size_t)s * Bv + b) * HLv + i];
    __syncthreads();
    if (f < FUT) {
        float a = blin[f];
        #pragma unroll 8
        for (int k = 0; k < HLv; k++) a += hs[k] * wlin[f * HLv + k];
        out[((size_t)b * NHv + s) * FUT + f] = lrelu(a);
    }
}

// =====================================================================
extern "C" void kernel_launch(void* const* d_in, const int* in_sizes, int n_in,
                              void* d_out, int out_size) {
    const float* meteo = (const float*)d_in[0];
    const float* hydro = (const float*)d_in[1];
    if (in_sizes[0] == Bv * Tv * NHv) {
        hydro = (const float*)d_in[0];
        meteo = (const float*)d_in[1];
    }
    const void*  ei    = d_in[2];
    const float* Wr    = (const float*)d_in[3];
    const float* Wl    = (const float*)d_in[4];
    const float* bgnn  = (const float*)d_in[5];
    const float* Wih   = (const float*)d_in[6];
    const float* Whh   = (const float*)d_in[7];
    if (in_sizes[6] == NHv * G4 * HLv) {
        Whh = (const float*)d_in[6];
        Wih = (const float*)d_in[7];
    }
    const float* bih   = (const float*)d_in[8];
    const float* bhh   = (const float*)d_in[9];
    const float* Wlin  = (const float*)d_in[10];
    const float* blin  = (const float*)d_in[11];
    float* out = (float*)d_out;

    cudaFuncSetAttribute(kC, cudaFuncAttributeMaxDynamicSharedMemorySize, SMEM_C);

    kE<<<1, 256>>>(ei);
    kT<<<dim3(4, 16, NHv), dim3(32, 8)>>>(Whh, G4, HLv, 0);
    kT<<<dim3(2, 16, NHv), dim3(32, 8)>>>(Wih, G4, HGv, 1);
    kB<<<dim3(Tv, NHv, 2), 128>>>(hydro, meteo, Wr, Wl, bgnn, bih, bhh);
    kC<<<128, 256, SMEM_C>>>();
    kD<<<NHv * Bv, 32>>>(Wlin, blin, out);
}

// round 13
// speedup vs baseline: 1.7727x; 1.7727x over previous
#include <cuda_runtime.h>
#include <cstdint>

#define Bv   32
#define Tv   168
#define NHv  32
#define NMv  64
#define Ev   384
#define HGv  64
#define HLv  128
#define G4   512
#define FUT  24
#define GT   (Bv*Tv)

#define RES   104        // Whh rows resident in smem (kC)
#define NREG  24         // Whh rows resident in registers (kC)

typedef unsigned long long u64t;

// -------- scratch --------
__device__ float d_whhT[(size_t)NHv * HLv * G4];          // [s][k][j]
__device__ float d_wihT[(size_t)NHv * HGv * G4];          // [s][k][j]
__device__ float d_xproj[(size_t)NHv * 4 * Tv * G4 * 8];  // [(s*4+bg)][t][j][bi]
__device__ float d_hfin[NHv * Bv * HLv];                  // [s][b][n]
__device__ int   d_csr_off[NHv + 1];                      // edges grouped by hydro dst
__device__ int   d_csr_src[Ev];

__device__ __forceinline__ u64t pk2(float x, float y) {
    u64t r; asm("mov.b64 %0,{%1,%2};" : "=l"(r) : "f"(x), "f"(y)); return r;
}
__device__ __forceinline__ float2 up2(u64t v) {
    float2 f; asm("mov.b64 {%0,%1},%2;" : "=f"(f.x), "=f"(f.y) : "l"(v)); return f;
}
__device__ __forceinline__ u64t fma2(u64t a, u64t b, u64t c) {
    u64t r; asm("fma.rn.f32x2 %0,%1,%2,%3;" : "=l"(r) : "l"(a), "l"(b), "l"(c)); return r;
}
__device__ __forceinline__ float sigf(float x) {
    return __fdividef(1.0f, 1.0f + __expf(-x));
}
__device__ __forceinline__ float tanhfast(float x) {
    return 1.0f - 2.0f * __fdividef(1.0f, __expf(2.0f * x) + 1.0f);
}
__device__ __forceinline__ float lrelu(float v) { return v > 0.0f ? v : 0.01f * v; }

// =====================================================================
// kE: dtype-robust edge decode + PARALLEL smem CSR build.
// Same per-dst edge order as serial build => identical numerics.
// =====================================================================
__global__ void kE(const void* __restrict__ ei) {
    __shared__ int nz;
    __shared__ short es[Ev], ed[Ev];
    __shared__ int offs[NHv + 1], cnts[NHv];
    const int* w = (const int*)ei;
    int tid = threadIdx.x;  // 256
    if (tid == 0) nz = 0;
    __syncthreads();
    int cnt = 0;
    for (int i = tid; i < 2 * Ev; i += 256)
        if ((i & 1) && w[i] == 0) cnt++;
    for (int o = 16; o > 0; o >>= 1) cnt += __shfl_down_sync(0xffffffffu, cnt, o);
    if ((tid & 31) == 0) atomicAdd(&nz, cnt);
    __syncthreads();
    bool is64 = (nz > 100);
    for (int e = tid; e < Ev; e += 256) {
        es[e] = (short)(is64 ? (int)((const long long*)ei)[e] : w[e]);
        ed[e] = (short)(is64 ? (int)((const long long*)ei)[Ev + e] : w[Ev + e]);
    }
    __syncthreads();
    if (tid < NHv) {
        int c = 0;
        for (int e = 0; e < Ev; e++)
            if (ed[e] == tid) c++;
        cnts[tid] = c;
    }
    __syncthreads();
    if (tid == 0) {
        int a = 0;
        for (int s2 = 0; s2 < NHv; s2++) { offs[s2] = a; a += cnts[s2]; }
        offs[NHv] = a;
        d_csr_off[NHv] = a;
    }
    __syncthreads();
    if (tid < NHv) {
        d_csr_off[tid] = offs[tid];
        int p = offs[tid];
        for (int e = 0; e < Ev; e++)
            if (ed[e] == tid) d_csr_src[p++] = (int)es[e];
    }
}

// =====================================================================
// kT: tiled per-station transpose [s][J][K] -> [s][K][J]. which: 0=whh,1=wih
// =====================================================================
__global__ void kT(const float* __restrict__ src, int J, int K, int which) {
    __shared__ float tile[32][33];
    int s = blockIdx.z;
    int k0 = blockIdx.x * 32, j0 = blockIdx.y * 32;
    int tx = threadIdx.x, ty = threadIdx.y;
    const float* S = src + (size_t)s * J * K;
    float* D = (which == 0 ? d_whhT : d_wihT) + (size_t)s * J * K;
    #pragma unroll
    for (int dy = 0; dy < 32; dy += 8)
        tile[ty + dy][tx] = S[(size_t)(j0 + ty + dy) * K + (k0 + tx)];
    __syncthreads();
    #pragma unroll
    for (int dy = 0; dy < 32; dy += 8)
        D[(size_t)(k0 + ty + dy) * J + (j0 + tx)] = tile[tx][ty + dy];
}

// =====================================================================
// kB: fused GNN + input projection (exact Round-11 version, float4 weights).
// grid (t, s, z=bhalf), 128 threads; thread jj: 4 j's x 16 batches.
// =====================================================================
__global__ void __launch_bounds__(128) kB(
        const float* __restrict__ hyd, const float* __restrict__ met,
        const float* __restrict__ Wr, const float* __restrict__ Wl,
        const float* __restrict__ bg,
        const float* __restrict__ bih, const float* __restrict__ bhh) {
    int t = blockIdx.x, s = blockIdx.y, z = blockIdx.z;
    int jj = threadIdx.x;
    int j0 = jj * 4;
    __shared__ float hloc[64 * 20];  // [k][b16], pad to 20
    __shared__ float xs[16], ag[16];
    __shared__ float wr[HGv], wl[HGv], bb[HGv];

    if (jj < HGv) { wr[jj] = Wr[jj]; wl[jj] = Wl[jj]; bb[jj] = bg[jj]; }
    if (jj >= 112) {  // one thread per batch: GNN scalar gather via CSR
        int b = jj - 112;
        int gb = z * 16 + b;
        const float* hrow = hyd + ((size_t)gb * Tv + t) * NHv;
        const float* mrow = met + ((size_t)gb * Tv + t) * NMv;
        xs[b] = hrow[s];
        float a = 0.0f;
        int e0 = d_csr_off[s], e1 = d_csr_off[s + 1];
        for (int e = e0; e < e1; e++) {
            int sr = d_csr_src[e];
            a += (sr < NHv) ? hrow[sr] : mrow[sr - NHv];
        }
        ag[b] = a;
    }
    __syncthreads();

    #pragma unroll
    for (int r = 0; r < 8; r++) {
        int idx = jj + r * 128;          // 1024 = 64k x 16b
        int k = idx >> 4, b = idx & 15;
        hloc[k * 20 + b] = lrelu(xs[b] * wr[k] + ag[b] * wl[k] + bb[k]);
    }
    __syncthreads();

    u64t acc[4][8];
    {
        float4 b1 = *reinterpret_cast<const float4*>(&bih[s * G4 + j0]);
        float4 b2 = *reinterpret_cast<const float4*>(&bhh[s * G4 + j0]);
        float bv[4] = {b1.x + b2.x, b1.y + b2.y, b1.z + b2.z, b1.w + b2.w};
        #pragma unroll
        for (int jl = 0; jl < 4; jl++) {
            u64t bb2 = pk2(bv[jl], bv[jl]);
            #pragma unroll
            for (int q = 0; q < 8; q++) acc[jl][q] = bb2;
        }
    }

    const float* wT = d_wihT + (size_t)s * (HGv * G4);
    #pragma unroll 2
    for (int k = 0; k < 64; k++) {
        float4 w = *reinterpret_cast<const float4*>(&wT[k * G4 + j0]);
        float wv[4] = {w.x, w.y, w.z, w.w};
        const ulonglong2* hp = reinterpret_cast<const ulonglong2*>(&hloc[k * 20]);
        ulonglong2 h0 = hp[0], h1 = hp[1], h2 = hp[2], h3 = hp[3];
        #pragma unroll
        for (int jl = 0; jl < 4; jl++) {
            u64t W = pk2(wv[jl], wv[jl]);
            acc[jl][0] = fma2(h0.x, W, acc[jl][0]);
            acc[jl][1] = fma2(h0.y, W, acc[jl][1]);
            acc[jl][2] = fma2(h1.x, W, acc[jl][2]);
            acc[jl][3] = fma2(h1.y, W, acc[jl][3]);
            acc[jl][4] = fma2(h2.x, W, acc[jl][4]);
            acc[jl][5] = fma2(h2.y, W, acc[jl][5]);
            acc[jl][6] = fma2(h3.x, W, acc[jl][6]);
            acc[jl][7] = fma2(h3.y, W, acc[jl][7]);
        }
    }

    #pragma unroll
    for (int jl = 0; jl < 4; jl++) {
        #pragma unroll
        for (int half = 0; half < 2; half++) {
            float* base = &d_xproj[(((size_t)(s * 4 + z * 2 + half) * Tv + t) * G4
                                    + (j0 + jl)) * 8];
            ulonglong2 v0, v1;
            v0.x = acc[jl][half * 4 + 0]; v0.y = acc[jl][half * 4 + 1];
            v1.x = acc[jl][half * 4 + 2]; v1.y = acc[jl][half * 4 + 3];
            reinterpret_cast<ulonglong2*>(base)[0] = v0;
            reinterpret_cast<ulonglong2*>(base)[1] = v1;
        }
    }
}

// =====================================================================
// kC: recurrence (exact Round-8 winner). 128 blocks = (s, bg), 256 threads.
// =====================================================================
#define SMEM_C (RES * G4 * 4 + 2 * 1024 * 4)

extern __shared__ float smc[];

__global__ void __launch_bounds__(256) kC() {
    int blk = blockIdx.x;
    int s = blk >> 2, bg = blk & 3;
    int tid = threadIdx.x;
    int n = tid & 127;       // hidden unit
    int bh = tid >> 7;       // batch half: batches bh*4 .. bh*4+3

    float* wpk = smc;                   // [RES][128n][4g] packed
    float* hb0 = smc + RES * G4;        // [128n][8bi] double buffer
    float* hb1 = hb0 + 1024;

    const float* whhTs = d_whhT + (size_t)s * (HLv * G4);
    for (int i = tid; i < RES * G4; i += 256) {
        int k = i >> 9, q = i & 511;
        int nn = q >> 2, g = q & 3;
        wpk[i] = whhTs[(size_t)k * G4 + g * 128 + nn];
    }
    for (int i = tid; i < 1024; i += 256) hb0[i] = 0.0f;

    float wreg[NREG][4];
    #pragma unroll
    for (int r = 0; r < NREG; r++)
        #pragma unroll
        for (int g = 0; g < 4; g++)
            wreg[r][g] = whhTs[(size_t)(RES + r) * G4 + g * 128 + n];

    float c[4];
    #pragma unroll
    for (int q = 0; q < 4; q++) c[q] = 0.0f;

    const float* xp = d_xproj + (size_t)(s * 4 + bg) * Tv * (G4 * 8);
    float4 xc[4];
    #pragma unroll
    for (int g = 0; g < 4; g++)
        xc[g] = *reinterpret_cast<const float4*>(xp + (size_t)(n + g * 128) * 8 + bh * 4);

    float* hcur = hb0;
    float* hnxt = hb1;
    __syncthreads();

    for (int t = 0; t < Tv; t++) {
        u64t acc[8];
        #pragma unroll
        for (int g = 0; g < 4; g++) {
            acc[2 * g + 0] = pk2(xc[g].x, xc[g].y);
            acc[2 * g + 1] = pk2(xc[g].z, xc[g].w);
        }
        if (t < Tv - 1) {
            const float* xn = xp + (size_t)(t + 1) * (G4 * 8);
            #pragma unroll
            for (int g = 0; g < 4; g++)
                xc[g] = *reinterpret_cast<const float4*>(
                    xn + (size_t)(n + g * 128) * 8 + bh * 4);
        }

        #pragma unroll 4
        for (int k = 0; k < RES; k++) {
            float4 w = *reinterpret_cast<const float4*>(&wpk[k * G4 + n * 4]);
            ulonglong2 h = *reinterpret_cast<const ulonglong2*>(&hcur[k * 8 + bh * 4]);
            u64t W;
            W = pk2(w.x, w.x);
            acc[0] = fma2(h.x, W, acc[0]); acc[1] = fma2(h.y, W, acc[1]);
            W = pk2(w.y, w.y);
            acc[2] = fma2(h.x, W, acc[2]); acc[3] = fma2(h.y, W, acc[3]);
            W = pk2(w.z, w.z);
            acc[4] = fma2(h.x, W, acc[4]); acc[5] = fma2(h.y, W, acc[5]);
            W = pk2(w.w, w.w);
            acc[6] = fma2(h.x, W, acc[6]); acc[7] = fma2(h.y, W, acc[7]);
        }
        #pragma unroll
        for (int r = 0; r < NREG; r++) {
            int k = RES + r;
            ulonglong2 h = *reinterpret_cast<const ulonglong2*>(&hcur[k * 8 + bh * 4]);
            u64t W;
            W = pk2(wreg[r][0], wreg[r][0]);
            acc[0] = fma2(h.x, W, acc[0]); acc[1] = fma2(h.y, W, acc[1]);
            W = pk2(wreg[r][1], wreg[r][1]);
            acc[2] = fma2(h.x, W, acc[2]); acc[3] = fma2(h.y, W, acc[3]);
            W = pk2(wreg[r][2], wreg[r][2]);
            acc[4] = fma2(h.x, W, acc[4]); acc[5] = fma2(h.y, W, acc[5]);
            W = pk2(wreg[r][3], wreg[r][3]);
            acc[6] = fma2(h.x, W, acc[6]); acc[7] = fma2(h.y, W, acc[7]);
        }

        {
            float2 i0 = up2(acc[0]), i1 = up2(acc[1]);
            float2 f0 = up2(acc[2]), f1 = up2(acc[3]);
            float2 g0 = up2(acc[4]), g1 = up2(acc[5]);
            float2 o0 = up2(acc[6]), o1 = up2(acc[7]);
            float4 hv;
            c[0] = sigf(f0.x) * c[0] + sigf(i0.x) * tanhfast(g0.x);
            hv.x = sigf(o0.x) * tanhfast(c[0]);
            c[1] = sigf(f0.y) * c[1] + sigf(i0.y) * tanhfast(g0.y);
            hv.y = sigf(o0.y) * tanhfast(c[1]);
            c[2] = sigf(f1.x) * c[2] + sigf(i1.x) * tanhfast(g1.x);
            hv.z = sigf(o1.x) * tanhfast(c[2]);
            c[3] = sigf(f1.y) * c[3] + sigf(i1.y) * tanhfast(g1.y);
            hv.w = sigf(o1.y) * tanhfast(c[3]);
            *reinterpret_cast<float4*>(&hnxt[n * 8 + bh * 4]) = hv;
        }
        __syncthreads();
        float* tmp = hcur; hcur = hnxt; hnxt = tmp;
    }

    #pragma unroll
    for (int q = 0; q < 4; q++) {
        int b = bg * 8 + bh * 4 + q;
        d_hfin[((size_t)s * Bv + b) * HLv + n] = hcur[n * 8 + bh * 4 + q];
    }
}

// =====================================================================
// kD: final linear + lrelu
// =====================================================================
__global__ void kD(const float* __restrict__ wlin, const float* __restrict__ blin,
                   float* __restrict__ out) {
    int s = blockIdx.x >> 5, b = blockIdx.x & 31;
    int f = threadIdx.x;
    __shared__ float hs[HLv];
    for (int i = threadIdx.x; i < HLv; i += 32)
        hs[i] = d_hfin[((size_t)s * Bv + b) * HLv + i];
    __syncthreads();
    if (f < FUT) {
        float a = blin[f];
        #pragma unroll 8
        for (int k = 0; k < HLv; k++) a += hs[k] * wlin[f * HLv + k];
        out[((size_t)b * NHv + s) * FUT + f] = lrelu(a);
    }
}

// =====================================================================
extern "C" void kernel_launch(void* const* d_in, const int* in_sizes, int n_in,
                              void* d_out, int out_size) {
    const float* meteo = (const float*)d_in[0];
    const float* hydro = (const float*)d_in[1];
    if (in_sizes[0] == Bv * Tv * NHv) {
        hydro = (const float*)d_in[0];
        meteo = (const float*)d_in[1];
    }
    const void*  ei    = d_in[2];
    const float* Wr    = (const float*)d_in[3];
    const float* Wl    = (const float*)d_in[4];
    const float* bgnn  = (const float*)d_in[5];
    const float* Wih   = (const float*)d_in[6];
    const float* Whh   = (const float*)d_in[7];
    if (in_sizes[6] == NHv * G4 * HLv) {
        Whh = (const float*)d_in[6];
        Wih = (const float*)d_in[7];
    }
    const float* bih   = (const float*)d_in[8];
    const float* bhh   = (const float*)d_in[9];
    const float* Wlin  = (const float*)d_in[10];
    const float* blin  = (const float*)d_in[11];
    float* out = (float*)d_out;

    cudaFuncSetAttribute(kC, cudaFuncAttributeMaxDynamicSharedMemorySize, SMEM_C);

    kE<<<1, 256>>>(ei);
    kT<<<dim3(4, 16, NHv), dim3(32, 8)>>>(Whh, G4, HLv, 0);
    kT<<<dim3(2, 16, NHv), dim3(32, 8)>>>(Wih, G4, HGv, 1);
    kB<<<dim3(Tv, NHv, 2), 128>>>(hydro, meteo, Wr, Wl, bgnn, bih, bhh);
    kC<<<128, 256, SMEM_C>>>();
    kD<<<NHv * Bv, 32>>>(Wlin, blin, out);
}

// round 15
// speedup vs baseline: 1.8554x; 1.0467x over previous
#include <cuda_runtime.h>
#include <cstdint>

#define Bv   32
#define Tv   168
#define NHv  32
#define NMv  64
#define Ev   384
#define HGv  64
#define HLv  128
#define G4   512
#define FUT  24
#define GT   (Bv*Tv)

#define RES   104        // Whh rows resident in smem (kC)
#define NREG  24         // Whh rows resident in registers (kC)

typedef unsigned long long u64t;

// -------- scratch --------
__device__ float d_whhT[(size_t)NHv * HLv * G4];          // [s][k][j]
__device__ float d_wihT[(size_t)NHv * HGv * G4];          // [s][k][j]
__device__ float d_xproj[(size_t)NHv * 4 * Tv * G4 * 8];  // [(s*4+bg)][t][j][bi]
__device__ float d_hfin[NHv * Bv * HLv];                  // [s][b][n]
__device__ int   d_csr_off[NHv + 1];                      // edges grouped by hydro dst
__device__ int   d_csr_src[Ev];

__device__ __forceinline__ u64t pk2(float x, float y) {
    u64t r; asm("mov.b64 %0,{%1,%2};" : "=l"(r) : "f"(x), "f"(y)); return r;
}
__device__ __forceinline__ float2 up2(u64t v) {
    float2 f; asm("mov.b64 {%0,%1},%2;" : "=f"(f.x), "=f"(f.y) : "l"(v)); return f;
}
__device__ __forceinline__ u64t fma2(u64t a, u64t b, u64t c) {
    u64t r; asm("fma.rn.f32x2 %0,%1,%2,%3;" : "=l"(r) : "l"(a), "l"(b), "l"(c)); return r;
}
__device__ __forceinline__ float sigf(float x) {
    return __fdividef(1.0f, 1.0f + __expf(-x));
}
__device__ __forceinline__ float tanhfast(float x) {
    return 1.0f - 2.0f * __fdividef(1.0f, __expf(2.0f * x) + 1.0f);
}
__device__ __forceinline__ float lrelu(float v) { return v > 0.0f ? v : 0.01f * v; }

// =====================================================================
// kE: dtype-robust edge decode + PARALLEL smem CSR build.
// =====================================================================
__global__ void kE(const void* __restrict__ ei) {
    __shared__ int nz;
    __shared__ short es[Ev], ed[Ev];
    __shared__ int offs[NHv + 1], cnts[NHv];
    const int* w = (const int*)ei;
    int tid = threadIdx.x;  // 256
    if (tid == 0) nz = 0;
    __syncthreads();
    int cnt = 0;
    for (int i = tid; i < 2 * Ev; i += 256)
        if ((i & 1) && w[i] == 0) cnt++;
    for (int o = 16; o > 0; o >>= 1) cnt += __shfl_down_sync(0xffffffffu, cnt, o);
    if ((tid & 31) == 0) atomicAdd(&nz, cnt);
    __syncthreads();
    bool is64 = (nz > 100);
    for (int e = tid; e < Ev; e += 256) {
        es[e] = (short)(is64 ? (int)((const long long*)ei)[e] : w[e]);
        ed[e] = (short)(is64 ? (int)((const long long*)ei)[Ev + e] : w[Ev + e]);
    }
    __syncthreads();
    if (tid < NHv) {
        int c = 0;
        for (int e = 0; e < Ev; e++)
            if (ed[e] == tid) c++;
        cnts[tid] = c;
    }
    __syncthreads();
    if (tid == 0) {
        int a = 0;
        for (int s2 = 0; s2 < NHv; s2++) { offs[s2] = a; a += cnts[s2]; }
        offs[NHv] = a;
        d_csr_off[NHv] = a;
    }
    __syncthreads();
    if (tid < NHv) {
        d_csr_off[tid] = offs[tid];
        int p = offs[tid];
        for (int e = 0; e < Ev; e++)
            if (ed[e] == tid) d_csr_src[p++] = (int)es[e];
    }
}

// =====================================================================
// kT: tiled per-station transpose [s][J][K] -> [s][K][J]. which: 0=whh,1=wih
// =====================================================================
__global__ void kT(const float* __restrict__ src, int J, int K, int which) {
    __shared__ float tile[32][33];
    int s = blockIdx.z;
    int k0 = blockIdx.x * 32, j0 = blockIdx.y * 32;
    int tx = threadIdx.x, ty = threadIdx.y;
    const float* S = src + (size_t)s * J * K;
    float* D = (which == 0 ? d_whhT : d_wihT) + (size_t)s * J * K;
    #pragma unroll
    for (int dy = 0; dy < 32; dy += 8)
        tile[ty + dy][tx] = S[(size_t)(j0 + ty + dy) * K + (k0 + tx)];
    __syncthreads();
    #pragma unroll
    for (int dy = 0; dy < 32; dy += 8)
        D[(size_t)(k0 + ty + dy) * J + (j0 + tx)] = tile[tx][ty + dy];
}

// =====================================================================
// kB: fused GNN + input projection. grid (t, s, z=bhalf), 256 threads.
// Thread jj owns j = {2jj, 2jj+1} x 16 batches: acc halves to 32 u64
// (~80 regs -> 3 blocks/SM vs 122 regs/24% occ before). Same k-ascending
// accumulation order => numerics identical to R13.
// =====================================================================
__global__ void __launch_bounds__(256) kB(
        const float* __restrict__ hyd, const float* __restrict__ met,
        const float* __restrict__ Wr, const float* __restrict__ Wl,
        const float* __restrict__ bg,
        const float* __restrict__ bih, const float* __restrict__ bhh) {
    int t = blockIdx.x, s = blockIdx.y, z = blockIdx.z;
    int jj = threadIdx.x;
    int j0 = jj * 2;
    __shared__ float hloc[64 * 20];  // [k][b16], pad to 20
    __shared__ float xs[16], ag[16];
    __shared__ float wr[HGv], wl[HGv], bb[HGv];

    if (jj < HGv) { wr[jj] = Wr[jj]; wl[jj] = Wl[jj]; bb[jj] = bg[jj]; }
    if (jj >= 240) {  // one thread per batch: GNN scalar gather via CSR
        int b = jj - 240;
        int gb = z * 16 + b;
        const float* hrow = hyd + ((size_t)gb * Tv + t) * NHv;
        const float* mrow = met + ((size_t)gb * Tv + t) * NMv;
        xs[b] = hrow[s];
        float a = 0.0f;
        int e0 = d_csr_off[s], e1 = d_csr_off[s + 1];
        for (int e = e0; e < e1; e++) {
            int sr = d_csr_src[e];
            a += (sr < NHv) ? hrow[sr] : mrow[sr - NHv];
        }
        ag[b] = a;
    }
    __syncthreads();

    {   // 1024 = 64k x 16b entries, one per thread x4... 256 threads x 4 entries
        #pragma unroll
        for (int r = 0; r < 4; r++) {
            int idx = jj + r * 256;
            int k = idx >> 4, b = idx & 15;
            hloc[k * 20 + b] = lrelu(xs[b] * wr[k] + ag[b] * wl[k] + bb[k]);
        }
    }
    __syncthreads();

    u64t acc[2][8];
    {
        float2 b1 = *reinterpret_cast<const float2*>(&bih[s * G4 + j0]);
        float2 b2 = *reinterpret_cast<const float2*>(&bhh[s * G4 + j0]);
        float bv[2] = {b1.x + b2.x, b1.y + b2.y};
        #pragma unroll
        for (int jl = 0; jl < 2; jl++) {
            u64t bb2 = pk2(bv[jl], bv[jl]);
            #pragma unroll
            for (int q = 0; q < 8; q++) acc[jl][q] = bb2;
        }
    }

    const float* wT = d_wihT + (size_t)s * (HGv * G4);
    #pragma unroll 4
    for (int k = 0; k < 64; k++) {
        float2 w = *reinterpret_cast<const float2*>(&wT[k * G4 + j0]);
        float wv[2] = {w.x, w.y};
        const ulonglong2* hp = reinterpret_cast<const ulonglong2*>(&hloc[k * 20]);
        ulonglong2 h0 = hp[0], h1 = hp[1], h2 = hp[2], h3 = hp[3];
        #pragma unroll
        for (int jl = 0; jl < 2; jl++) {
            u64t W = pk2(wv[jl], wv[jl]);
            acc[jl][0] = fma2(h0.x, W, acc[jl][0]);
            acc[jl][1] = fma2(h0.y, W, acc[jl][1]);
            acc[jl][2] = fma2(h1.x, W, acc[jl][2]);
            acc[jl][3] = fma2(h1.y, W, acc[jl][3]);
            acc[jl][4] = fma2(h2.x, W, acc[jl][4]);
            acc[jl][5] = fma2(h2.y, W, acc[jl][5]);
            acc[jl][6] = fma2(h3.x, W, acc[jl][6]);
            acc[jl][7] = fma2(h3.y, W, acc[jl][7]);
        }
    }

    #pragma unroll
    for (int jl = 0; jl < 2; jl++) {
        #pragma unroll
        for (int half = 0; half < 2; half++) {
            float* base = &d_xproj[(((size_t)(s * 4 + z * 2 + half) * Tv + t) * G4
                                    + (j0 + jl)) * 8];
            ulonglong2 v0, v1;
            v0.x = acc[jl][half * 4 + 0]; v0.y = acc[jl][half * 4 + 1];
            v1.x = acc[jl][half * 4 + 2]; v1.y = acc[jl][half * 4 + 3];
            reinterpret_cast<ulonglong2*>(base)[0] = v0;
            reinterpret_cast<ulonglong2*>(base)[1] = v1;
        }
    }
}

// =====================================================================
// kC: recurrence (exact Round-8 winner). 128 blocks = (s, bg), 256 threads.
// =====================================================================
#define SMEM_C (RES * G4 * 4 + 2 * 1024 * 4)

extern __shared__ float smc[];

__global__ void __launch_bounds__(256) kC() {
    int blk = blockIdx.x;
    int s = blk >> 2, bg = blk & 3;
    int tid = threadIdx.x;
    int n = tid & 127;       // hidden unit
    int bh = tid >> 7;       // batch half: batches bh*4 .. bh*4+3

    float* wpk = smc;                   // [RES][128n][4g] packed
    float* hb0 = smc + RES * G4;        // [128n][8bi] double buffer
    float* hb1 = hb0 + 1024;

    const float* whhTs = d_whhT + (size_t)s * (HLv * G4);
    for (int i = tid; i < RES * G4; i += 256) {
        int k = i >> 9, q = i & 511;
        int nn = q >> 2, g = q & 3;
        wpk[i] = whhTs[(size_t)k * G4 + g * 128 + nn];
    }
    for (int i = tid; i < 1024; i += 256) hb0[i] = 0.0f;

    float wreg[NREG][4];
    #pragma unroll
    for (int r = 0; r < NREG; r++)
        #pragma unroll
        for (int g = 0; g < 4; g++)
            wreg[r][g] = whhTs[(size_t)(RES + r) * G4 + g * 128 + n];

    float c[4];
    #pragma unroll
    for (int q = 0; q < 4; q++) c[q] = 0.0f;

    const float* xp = d_xproj + (size_t)(s * 4 + bg) * Tv * (G4 * 8);
    float4 xc[4];
    #pragma unroll
    for (int g = 0; g < 4; g++)
        xc[g] = *reinterpret_cast<const float4*>(xp + (size_t)(n + g * 128) * 8 + bh * 4);

    float* hcur = hb0;
    float* hnxt = hb1;
    __syncthreads();

    for (int t = 0; t < Tv; t++) {
        u64t acc[8];
        #pragma unroll
        for (int g = 0; g < 4; g++) {
            acc[2 * g + 0] = pk2(xc[g].x, xc[g].y);
            acc[2 * g + 1] = pk2(xc[g].z, xc[g].w);
        }
        if (t < Tv - 1) {
            const float* xn = xp + (size_t)(t + 1) * (G4 * 8);
            #pragma unroll
            for (int g = 0; g < 4; g++)
                xc[g] = *reinterpret_cast<const float4*>(
                    xn + (size_t)(n + g * 128) * 8 + bh * 4);
        }

        #pragma unroll 4
        for (int k = 0; k < RES; k++) {
            float4 w = *reinterpret_cast<const float4*>(&wpk[k * G4 + n * 4]);
            ulonglong2 h = *reinterpret_cast<const ulonglong2*>(&hcur[k * 8 + bh * 4]);
            u64t W;
            W = pk2(w.x, w.x);
            acc[0] = fma2(h.x, W, acc[0]); acc[1] = fma2(h.y, W, acc[1]);
            W = pk2(w.y, w.y);
            acc[2] = fma2(h.x, W, acc[2]); acc[3] = fma2(h.y, W, acc[3]);
            W = pk2(w.z, w.z);
            acc[4] = fma2(h.x, W, acc[4]); acc[5] = fma2(h.y, W, acc[5]);
            W = pk2(w.w, w.w);
            acc[6] = fma2(h.x, W, acc[6]); acc[7] = fma2(h.y, W, acc[7]);
        }
        #pragma unroll
        for (int r = 0; r < NREG; r++) {
            int k = RES + r;
            ulonglong2 h = *reinterpret_cast<const ulonglong2*>(&hcur[k * 8 + bh * 4]);
            u64t W;
            W = pk2(wreg[r][0], wreg[r][0]);
            acc[0] = fma2(h.x, W, acc[0]); acc[1] = fma2(h.y, W, acc[1]);
            W = pk2(wreg[r][1], wreg[r][1]);
            acc[2] = fma2(h.x, W, acc[2]); acc[3] = fma2(h.y, W, acc[3]);
            W = pk2(wreg[r][2], wreg[r][2]);
            acc[4] = fma2(h.x, W, acc[4]); acc[5] = fma2(h.y, W, acc[5]);
            W = pk2(wreg[r][3], wreg[r][3]);
            acc[6] = fma2(h.x, W, acc[6]); acc[7] = fma2(h.y, W, acc[7]);
        }

        {
            float2 i0 = up2(acc[0]), i1 = up2(acc[1]);
            float2 f0 = up2(acc[2]), f1 = up2(acc[3]);
            float2 g0 = up2(acc[4]), g1 = up2(acc[5]);
            float2 o0 = up2(acc[6]), o1 = up2(acc[7]);
            float4 hv;
            c[0] = sigf(f0.x) * c[0] + sigf(i0.x) * tanhfast(g0.x);
            hv.x = sigf(o0.x) * tanhfast(c[0]);
            c[1] = sigf(f0.y) * c[1] + sigf(i0.y) * tanhfast(g0.y);
            hv.y = sigf(o0.y) * tanhfast(c[1]);
            c[2] = sigf(f1.x) * c[2] + sigf(i1.x) * tanhfast(g1.x);
            hv.z = sigf(o1.x) * tanhfast(c[2]);
            c[3] = sigf(f1.y) * c[3] + sigf(i1.y) * tanhfast(g1.y);
            hv.w = sigf(o1.y) * tanhfast(c[3]);
            *reinterpret_cast<float4*>(&hnxt[n * 8 + bh * 4]) = hv;
        }
        __syncthreads();
        float* tmp = hcur; hcur = hnxt; hnxt = tmp;
    }

    #pragma unroll
    for (int q = 0; q < 4; q++) {
        int b = bg * 8 + bh * 4 + q;
        d_hfin[((size_t)s * Bv + b) * HLv + n] = hcur[n * 8 + bh * 4 + q];
    }
}

// =====================================================================
// kD: final linear + lrelu
// =====================================================================
__global__ void kD(const float* __restrict__ wlin, const float* __restrict__ blin,
                   float* __restrict__ out) {
    int s = blockIdx.x >> 5, b = blockIdx.x & 31;
    int f = threadIdx.x;
    __shared__ float hs[HLv];
    for (int i = threadIdx.x; i < HLv; i += 32)
        hs[i] = d_hfin[((size_t)s * Bv + b) * HLv + i];
    __syncthreads();
    if (f < FUT) {
        float a = blin[f];
        #pragma unroll 8
        for (int k = 0; k < HLv; k++) a += hs[k] * wlin[f * HLv + k];
        out[((size_t)b * NHv + s) * FUT + f] = lrelu(a);
    }
}

// =====================================================================
extern "C" void kernel_launch(void* const* d_in, const int* in_sizes, int n_in,
                              void* d_out, int out_size) {
    const float* meteo = (const float*)d_in[0];
    const float* hydro = (const float*)d_in[1];
    if (in_sizes[0] == Bv * Tv * NHv) {
        hydro = (const float*)d_in[0];
        meteo = (const float*)d_in[1];
    }
    const void*  ei    = d_in[2];
    const float* Wr    = (const float*)d_in[3];
    const float* Wl    = (const float*)d_in[4];
    const float* bgnn  = (const float*)d_in[5];
    const float* Wih   = (const float*)d_in[6];
    const float* Whh   = (const float*)d_in[7];
    if (in_sizes[6] == NHv * G4 * HLv) {
        Whh = (const float*)d_in[6];
        Wih = (const float*)d_in[7];
    }
    const float* bih   = (const float*)d_in[8];
    const float* bhh   = (const float*)d_in[9];
    const float* Wlin  = (const float*)d_in[10];
    const float* blin  = (const float*)d_in[11];
    float* out = (float*)d_out;

    cudaFuncSetAttribute(kC, cudaFuncAttributeMaxDynamicSharedMemorySize, SMEM_C);

    kE<<<1, 256>>>(ei);
    kT<<<dim3(4, 16, NHv), dim3(32, 8)>>>(Whh, G4, HLv, 0);
    kT<<<dim3(2, 16, NHv), dim3(32, 8)>>>(Wih, G4, HGv, 1);
    kB<<<dim3(Tv, NHv, 2), 256>>>(hydro, meteo, Wr, Wl, bgnn, bih, bhh);
    kC<<<128, 256, SMEM_C>>>();
    kD<<<NHv * Bv, 32>>>(Wlin, blin, out);
}